// round 2
// baseline (speedup 1.0000x reference)
#include <cuda_runtime.h>
#include <math.h>

// Problem constants
#define BB 8
#define CH 512
#define HW 4096
#define NN 2048
#define M3 768   // stacked theta|phi|g output channels (3*256)

// ---------------- scratch (device globals; no allocation allowed) ----------------
__device__ float d_wpack[M3 * CH];                        // stacked [theta;phi;g] weights
__device__ float d_tpg[(size_t)BB * M3 * HW];             // conv outputs, 100.7MB
__device__ float d_attn[(size_t)BB * NN * NN];            // attention logits, 134MB
__device__ float d_m[BB * NN];                            // per-column max
__device__ float d_rinv[BB * NN];                         // per-column 1/sumexp
__device__ float d_pm[8 * BB * NN];                       // partial max (8 segments)
__device__ float d_ps[8 * BB * NN];                       // partial sumexp
__device__ float d_y[(size_t)BB * CH * NN];               // Yt = (attn_sm @ g^T)^T, 33.5MB

// ---------------- packed fp32x2 helpers (sm_103: doubles FFMA throughput) --------
__device__ __forceinline__ unsigned long long pk2(float lo, float hi) {
    unsigned long long r;
    asm("mov.b64 %0, {%1, %2};" : "=l"(r) : "f"(lo), "f"(hi));
    return r;
}
__device__ __forceinline__ void upk2(unsigned long long v, float& lo, float& hi) {
    asm("mov.b64 {%0, %1}, %2;" : "=f"(lo), "=f"(hi) : "l"(v));
}
__device__ __forceinline__ void fma2(unsigned long long& c, unsigned long long a,
                                     unsigned long long b) {
    asm("fma.rn.f32x2 %0, %1, %2, %0;" : "+l"(c) : "l"(a), "l"(b));
}

// ---------------- shared 128x128x8 SGEMM core (8x8 microtile, FFMA2) -------------
__device__ __forceinline__ void mm_core(float As[8][128], float Bs[8][128],
                                        int ty, int tx, unsigned long long acc[8][4]) {
#pragma unroll
    for (int kk = 0; kk < 8; kk++) {
        float4 a0 = *(const float4*)&As[kk][ty * 8];
        float4 a1 = *(const float4*)&As[kk][ty * 8 + 4];
        float4 b0 = *(const float4*)&Bs[kk][tx * 8];
        float4 b1 = *(const float4*)&Bs[kk][tx * 8 + 4];
        unsigned long long a2[8];
        a2[0] = pk2(a0.x, a0.x); a2[1] = pk2(a0.y, a0.y);
        a2[2] = pk2(a0.z, a0.z); a2[3] = pk2(a0.w, a0.w);
        a2[4] = pk2(a1.x, a1.x); a2[5] = pk2(a1.y, a1.y);
        a2[6] = pk2(a1.z, a1.z); a2[7] = pk2(a1.w, a1.w);
        unsigned long long b2[4];
        b2[0] = pk2(b0.x, b0.y); b2[1] = pk2(b0.z, b0.w);
        b2[2] = pk2(b1.x, b1.y); b2[3] = pk2(b1.z, b1.w);
#pragma unroll
        for (int u = 0; u < 8; u++)
#pragma unroll
            for (int v = 0; v < 4; v++) fma2(acc[u][v], a2[u], b2[v]);
    }
}

__device__ __forceinline__ void store_row(float* C, unsigned long long accrow[4]) {
    float4 c0, c1;
    upk2(accrow[0], c0.x, c0.y); upk2(accrow[1], c0.z, c0.w);
    upk2(accrow[2], c1.x, c1.y); upk2(accrow[3], c1.z, c1.w);
    *(float4*)C = c0;
    *(float4*)(C + 4) = c1;
}

// ---------------- kernel 0: pack weights into stacked [theta; phi; g] ------------
__global__ void k_pack(const float* __restrict__ wphi, const float* __restrict__ wtheta,
                       const float* __restrict__ wg) {
    int idx = blockIdx.x * 256 + threadIdx.x;
    if (idx >= M3 * CH) return;
    int o = idx / CH;
    float v;
    if (o < 256)       v = wtheta[idx];
    else if (o < 512)  v = wphi[idx - 256 * CH];
    else               v = wg[idx - 512 * CH];
    d_wpack[idx] = v;
}

// ---------------- kernel 1: conv GEMM  tpg[b] = Wpack(768x512) @ x[b](512x4096) --
__global__ __launch_bounds__(256) void k_conv(const float* __restrict__ x) {
    int b = blockIdx.z, bm = blockIdx.y, bn = blockIdx.x;
    __shared__ float As[8][128], Bs[8][128];
    int t = threadIdx.x;
    int arow = t >> 1, acol = (t & 1) * 4;
    int brow = t >> 5, bcol = (t & 31) * 4;
    int tx = t & 15, ty = t >> 4;
    unsigned long long acc[8][4];
#pragma unroll
    for (int u = 0; u < 8; u++)
#pragma unroll
        for (int v = 0; v < 4; v++) acc[u][v] = 0ull;

    const float* Ag = d_wpack + (bm * 128 + arow) * CH + acol;
    const float* Bg = x + (size_t)b * CH * HW + brow * HW + bn * 128 + bcol;
    for (int kt = 0; kt < CH / 8; kt++) {
        float4 av = *(const float4*)Ag; Ag += 8;
        float4 bv = *(const float4*)Bg; Bg += 8 * HW;
        __syncthreads();
        As[acol + 0][arow] = av.x; As[acol + 1][arow] = av.y;
        As[acol + 2][arow] = av.z; As[acol + 3][arow] = av.w;
        *(float4*)&Bs[brow][bcol] = bv;
        __syncthreads();
        mm_core(As, Bs, ty, tx, acc);
    }
    float* C = d_tpg + (size_t)b * M3 * HW + (size_t)(bm * 128 + ty * 8) * HW + bn * 128 + tx * 8;
#pragma unroll
    for (int u = 0; u < 8; u++) store_row(C + (size_t)u * HW, acc[u]);
}

// ---------------- kernel 2: attn[b] = theta^T @ phi  (2048x2048, K=512) ----------
// theta,phi stored k-major (512 rows x 2048 cols), so both tiles load like "B".
__global__ __launch_bounds__(256) void k_attn() {
    int b = blockIdx.z, bm = blockIdx.y, bn = blockIdx.x;
    __shared__ float As[8][128], Bs[8][128];
    int t = threadIdx.x;
    int krow = t >> 5, kcol = (t & 31) * 4;
    int tx = t & 15, ty = t >> 4;
    unsigned long long acc[8][4];
#pragma unroll
    for (int u = 0; u < 8; u++)
#pragma unroll
        for (int v = 0; v < 4; v++) acc[u][v] = 0ull;

    const float* Tb = d_tpg + (size_t)b * M3 * HW;         // theta as (512 x 2048)
    const float* Pb = Tb + 256 * HW;                       // phi   as (512 x 2048)
    const float* Ag = Tb + krow * NN + bm * 128 + kcol;
    const float* Bg = Pb + krow * NN + bn * 128 + kcol;
    for (int kt = 0; kt < CH / 8; kt++) {
        float4 av = *(const float4*)Ag; Ag += 8 * NN;
        float4 bv = *(const float4*)Bg; Bg += 8 * NN;
        __syncthreads();
        *(float4*)&As[krow][kcol] = av;
        *(float4*)&Bs[krow][kcol] = bv;
        __syncthreads();
        mm_core(As, Bs, ty, tx, acc);
    }
    float* C = d_attn + (size_t)b * NN * NN + (size_t)(bm * 128 + ty * 8) * NN + bn * 128 + tx * 8;
#pragma unroll
    for (int u = 0; u < 8; u++) store_row(C + (size_t)u * NN, acc[u]);
}

// ---------------- kernel 3a: segmented column max/sumexp (softmax over rows) -----
__global__ void k_stats_part() {
    int b = blockIdx.z, seg = blockIdx.y;
    int j = blockIdx.x * 256 + threadIdx.x;
    const float* p = d_attn + (size_t)b * NN * NN + (size_t)(seg * 256) * NN + j;
    float m = -INFINITY, s = 0.f;
    for (int i = 0; i < 256; i++) {
        float v = p[(size_t)i * NN];
        float nm = fmaxf(m, v);
        s = s * __expf(m - nm) + __expf(v - nm);
        m = nm;
    }
    d_pm[(seg * BB + b) * NN + j] = m;
    d_ps[(seg * BB + b) * NN + j] = s;
}

// ---------------- kernel 3b: combine segment stats -> m_j, 1/sum_j ---------------
__global__ void k_stats_comb() {
    int b = blockIdx.y;
    int j = blockIdx.x * 256 + threadIdx.x;
    float M = -INFINITY;
#pragma unroll
    for (int s = 0; s < 8; s++) M = fmaxf(M, d_pm[(s * BB + b) * NN + j]);
    float S = 0.f;
#pragma unroll
    for (int s = 0; s < 8; s++)
        S += d_ps[(s * BB + b) * NN + j] * __expf(d_pm[(s * BB + b) * NN + j] - M);
    d_m[b * NN + j] = M;
    d_rinv[b * NN + j] = 1.f / S;
}

// ---------------- kernel 4: Yt[b] = g(512x2048) @ softmax(attn)^T  (K=2048) ------
// B tile = exp(attn[i,j]-m_j)*rinv_j computed on the fly (attn never rewritten).
__global__ __launch_bounds__(256) void k_av() {
    int b = blockIdx.z, bm = blockIdx.y, bn = blockIdx.x;
    __shared__ float As[8][128], Bs[8][128];
    int t = threadIdx.x;
    int arow = t >> 1, acol = (t & 1) * 4;
    int irow = t >> 1, jcol = (t & 1) * 4;
    int tx = t & 15, ty = t >> 4;
    unsigned long long acc[8][4];
#pragma unroll
    for (int u = 0; u < 8; u++)
#pragma unroll
        for (int v = 0; v < 4; v++) acc[u][v] = 0ull;

    const float* Gb = d_tpg + (size_t)b * M3 * HW + 512 * HW;  // g as (512 x 2048)
    const float* Ab = d_attn + (size_t)b * NN * NN;
    const float* mb = d_m + b * NN;
    const float* rb = d_rinv + b * NN;
    const float* Ag = Gb + (size_t)(bm * 128 + arow) * NN + acol;
    const float* Bg = Ab + (size_t)(bn * 128 + irow) * NN + jcol;
    for (int kt = 0; kt < NN / 8; kt++) {
        float4 av = *(const float4*)Ag; Ag += 8;
        float4 bv = *(const float4*)Bg; Bg += 8;
        float4 mv = *(const float4*)(mb + kt * 8 + jcol);
        float4 rv = *(const float4*)(rb + kt * 8 + jcol);
        float e0 = __expf(bv.x - mv.x) * rv.x;
        float e1 = __expf(bv.y - mv.y) * rv.y;
        float e2 = __expf(bv.z - mv.z) * rv.z;
        float e3 = __expf(bv.w - mv.w) * rv.w;
        __syncthreads();
        As[acol + 0][arow] = av.x; As[acol + 1][arow] = av.y;
        As[acol + 2][arow] = av.z; As[acol + 3][arow] = av.w;
        Bs[jcol + 0][irow] = e0; Bs[jcol + 1][irow] = e1;
        Bs[jcol + 2][irow] = e2; Bs[jcol + 3][irow] = e3;
        __syncthreads();
        mm_core(As, Bs, ty, tx, acc);
    }
    float* C = d_y + (size_t)b * CH * NN + (size_t)(bm * 128 + ty * 8) * NN + bn * 128 + tx * 8;
#pragma unroll
    for (int u = 0; u < 8; u++) store_row(C + (size_t)u * NN, acc[u]);
}

// ---------------- kernel 5: out[b] = w_mask(512x256) @ Y[b](256x4096) + x --------
__global__ __launch_bounds__(256) void k_mask(const float* __restrict__ wmask,
                                              const float* __restrict__ x,
                                              float* __restrict__ out) {
    int b = blockIdx.z, bm = blockIdx.y, bn = blockIdx.x;
    __shared__ float As[8][128], Bs[8][128];
    int t = threadIdx.x;
    int arow = t >> 1, acol = (t & 1) * 4;
    int brow = t >> 5, bcol = (t & 31) * 4;
    int tx = t & 15, ty = t >> 4;
    unsigned long long acc[8][4];
#pragma unroll
    for (int u = 0; u < 8; u++)
#pragma unroll
        for (int v = 0; v < 4; v++) acc[u][v] = 0ull;

    const float* Yb = d_y + (size_t)b * CH * NN;           // viewed as (256 x 4096)
    const float* Ag = wmask + (bm * 128 + arow) * 256 + acol;
    const float* Bg = Yb + brow * HW + bn * 128 + bcol;
    for (int kt = 0; kt < 256 / 8; kt++) {
        float4 av = *(const float4*)Ag; Ag += 8;
        float4 bv = *(const float4*)Bg; Bg += 8 * HW;
        __syncthreads();
        As[acol + 0][arow] = av.x; As[acol + 1][arow] = av.y;
        As[acol + 2][arow] = av.z; As[acol + 3][arow] = av.w;
        *(float4*)&Bs[brow][bcol] = bv;
        __syncthreads();
        mm_core(As, Bs, ty, tx, acc);
    }
#pragma unroll
    for (int u = 0; u < 8; u++) {
        size_t base = (size_t)b * CH * HW + (size_t)(bm * 128 + ty * 8 + u) * HW + bn * 128 + tx * 8;
        float4 c0, c1;
        upk2(acc[u][0], c0.x, c0.y); upk2(acc[u][1], c0.z, c0.w);
        upk2(acc[u][2], c1.x, c1.y); upk2(acc[u][3], c1.z, c1.w);
        float4 x0 = *(const float4*)(x + base);
        float4 x1 = *(const float4*)(x + base + 4);
        c0.x += x0.x; c0.y += x0.y; c0.z += x0.z; c0.w += x0.w;
        c1.x += x1.x; c1.y += x1.y; c1.z += x1.z; c1.w += x1.w;
        *(float4*)(out + base) = c0;
        *(float4*)(out + base + 4) = c1;
    }
}

// ---------------- launch ---------------------------------------------------------
extern "C" void kernel_launch(void* const* d_in, const int* in_sizes, int n_in,
                              void* d_out, int out_size) {
    const float* x      = (const float*)d_in[0];
    const float* wphi   = (const float*)d_in[1];
    const float* wtheta = (const float*)d_in[2];
    const float* wg     = (const float*)d_in[3];
    const float* wmask  = (const float*)d_in[4];
    float* out = (float*)d_out;

    k_pack<<<(M3 * CH + 255) / 256, 256>>>(wphi, wtheta, wg);
    k_conv<<<dim3(HW / 128, M3 / 128, BB), 256>>>(x);
    k_attn<<<dim3(NN / 128, NN / 128, BB), 256>>>();
    k_stats_part<<<dim3(8, 8, BB), 256>>>();
    k_stats_comb<<<dim3(8, BB), 256>>>();
    k_av<<<dim3(NN / 128, CH / 128, BB), 256>>>();
    k_mask<<<dim3(HW / 128, CH / 128, BB), 256>>>(wmask, x, out);
}

// round 8
// speedup vs baseline: 2.2826x; 2.2826x over previous
#include <cuda_runtime.h>
#include <cuda_bf16.h>
#include <math.h>
#include <cstdint>
#include <cstddef>

#define BB 8
#define CH 512
#define HW 4096
#define NN 2048

// ================= scratch (device globals; allocation is forbidden) =============
__device__ __align__(256) __nv_bfloat16 g_Wp_h[768 * 512], g_Wp_l[768 * 512];
__device__ __align__(256) __nv_bfloat16 g_Wm_h[512 * 256], g_Wm_l[512 * 256];
__device__ __align__(256) __nv_bfloat16 g_Xt_h[(size_t)BB * HW * CH], g_Xt_l[(size_t)BB * HW * CH];
__device__ __align__(256) float         g_tpg[(size_t)BB * 768 * HW];
__device__ __align__(256) __nv_bfloat16 g_Tt_h[(size_t)BB * NN * CH], g_Tt_l[(size_t)BB * NN * CH];
__device__ __align__(256) __nv_bfloat16 g_Pt_h[(size_t)BB * NN * CH], g_Pt_l[(size_t)BB * NN * CH];
__device__ __align__(256) __nv_bfloat16 g_Gv_h[(size_t)BB * CH * NN], g_Gv_l[(size_t)BB * CH * NN];
__device__ __align__(256) float         g_attn[(size_t)BB * NN * NN];
__device__ __align__(256) __nv_bfloat16 g_P_h[(size_t)BB * NN * NN], g_P_l[(size_t)BB * NN * NN];
__device__ __align__(256) float         g_y[(size_t)BB * CH * NN];
__device__ __align__(256) __nv_bfloat16 g_Yt_h[(size_t)BB * HW * 256], g_Yt_l[(size_t)BB * HW * 256];
__device__ float g_m[BB * NN], g_rinv[BB * NN];
__device__ float g_pm[8 * BB * NN], g_ps[8 * BB * NN];

// ================= helpers ========================================================
__device__ __forceinline__ uint32_t smem_u32(const void* p) {
    uint32_t a;
    asm("{ .reg .u64 t; cvta.to.shared.u64 t, %1; cvt.u32.u64 %0, t; }" : "=r"(a) : "l"(p));
    return a;
}
#define CP_ASYNC16(s, g) \
    asm volatile("cp.async.cg.shared.global [%0], [%1], 16;" :: "r"(s), "l"(g))
#define CP_COMMIT() asm volatile("cp.async.commit_group;" ::: "memory")
#define CP_WAIT(n)  asm volatile("cp.async.wait_group %0;" :: "n"(n) : "memory")
#define LDSM4(r, addr) \
    asm volatile("ldmatrix.sync.aligned.m8n8.x4.shared.b16 {%0,%1,%2,%3}, [%4];" \
        : "=r"((r)[0]), "=r"((r)[1]), "=r"((r)[2]), "=r"((r)[3]) : "r"(addr))
#define MMA_BF16(c, a, b0_, b1_) \
    asm volatile("mma.sync.aligned.m16n8k16.row.col.f32.bf16.bf16.f32 " \
        "{%0,%1,%2,%3}, {%4,%5,%6,%7}, {%8,%9}, {%0,%1,%2,%3};" \
        : "+f"((c)[0]), "+f"((c)[1]), "+f"((c)[2]), "+f"((c)[3]) \
        : "r"((a)[0]), "r"((a)[1]), "r"((a)[2]), "r"((a)[3]), "r"(b0_), "r"(b1_))

// bf16 pack/split helpers
__device__ __forceinline__ uint32_t pack_bf(float lo, float hi) {
    uint32_t r;
    asm("cvt.rn.bf16x2.f32 %0, %1, %2;" : "=r"(r) : "f"(hi), "f"(lo));
    return r;
}
__device__ __forceinline__ float bf_lo(uint32_t p) { return __uint_as_float(p << 16); }
__device__ __forceinline__ float bf_hi(uint32_t p) { return __uint_as_float(p & 0xffff0000u); }
__device__ __forceinline__ void split16(const float* v, uint32_t* hp, uint32_t* lp) {
#pragma unroll
    for (int j = 0; j < 8; j++) {
        float a0 = v[2 * j], a1 = v[2 * j + 1];
        uint32_t hh = pack_bf(a0, a1);
        hp[j] = hh;
        lp[j] = pack_bf(a0 - bf_lo(hh), a1 - bf_hi(hh));
    }
}

// ================= 3-term bf16 HMMA GEMM ==========================================
// C[M,N] = sum_k A[m,k]*B[n,k]; A=Ah+Al, B=Bh+Bl (hi/lo bf16). Terms: hh + hl + lh.
// CTA tile 128x256, BK=32, 8 warps (2x4), warp tile 64x64. cp.async double buffer.
// SMEM per stage: Ah[128x80B] Al Bh[256x80B] Bl; 80B row stride => conflict-free
// ldmatrix (8 rows x 80B tile all 32 banks exactly).
#define BM 128
#define BN 256
#define BKT 32
static constexpr unsigned STAGE = 61440;      // 2*10240 + 2*20480
static constexpr unsigned GEMM_SMEM = 2 * STAGE;  // 122880

__global__ __launch_bounds__(256, 1)
void gemm_bf16x3(const __nv_bfloat16* __restrict__ Ah, const __nv_bfloat16* __restrict__ Al,
                 const __nv_bfloat16* __restrict__ Bh, const __nv_bfloat16* __restrict__ Bl,
                 float* __restrict__ C, const float* __restrict__ R,
                 int K, int ldc, size_t sA, size_t sB, size_t sC) {
    extern __shared__ char smem[];
    const int tid = threadIdx.x;
    const int wid = tid >> 5, lane = tid & 31;
    const int wm = wid >> 2, wn = wid & 3;
    const int b = blockIdx.z, bm = blockIdx.y, bn = blockIdx.x;
    const uint32_t sbase = smem_u32(smem);

    const __nv_bfloat16* A0h = Ah + sA * b + (size_t)(bm * BM) * K;
    const __nv_bfloat16* A0l = Al + sA * b + (size_t)(bm * BM) * K;
    const __nv_bfloat16* B0h = Bh + sB * b + (size_t)(bn * BN) * K;
    const __nv_bfloat16* B0l = Bl + sB * b + (size_t)(bn * BN) * K;

    float acc[4][8][4];
#pragma unroll
    for (int mf = 0; mf < 4; mf++)
#pragma unroll
        for (int nf = 0; nf < 8; nf++)
#pragma unroll
            for (int q = 0; q < 4; q++) acc[mf][nf][q] = 0.f;

    auto issue = [&](int kt) {
        const int koff = kt * BKT;
        const uint32_t sb = sbase + (uint32_t)(kt & 1) * STAGE;
#pragma unroll
        for (int i = 0; i < 12; i++) {
            int V = i * 256 + tid;
            const __nv_bfloat16* g;
            uint32_t s;
            if (V < 1024) {                       // A: 128 rows x 4 chunks x 2 halves
                int half = V >> 9, r = (V >> 2) & 127, c = V & 3;
                g = (half ? A0l : A0h) + (size_t)r * K + koff + c * 8;
                s = sb + (uint32_t)half * 10240u + (uint32_t)r * 80u + (uint32_t)c * 16u;
            } else {                              // B: 256 rows x 4 chunks x 2 halves
                int V2 = V - 1024;
                int half = V2 >> 10, r = (V2 >> 2) & 255, c = V2 & 3;
                g = (half ? B0l : B0h) + (size_t)r * K + koff + c * 8;
                s = sb + 20480u + (uint32_t)half * 20480u + (uint32_t)r * 80u + (uint32_t)c * 16u;
            }
            CP_ASYNC16(s, g);
        }
        CP_COMMIT();
    };

    const int KT = K / BKT;
    issue(0);
    for (int kt = 0; kt < KT; kt++) {
        if (kt + 1 < KT) { issue(kt + 1); CP_WAIT(1); }
        else             { CP_WAIT(0); }
        __syncthreads();
        const uint32_t sb = sbase + (uint32_t)(kt & 1) * STAGE;
        const uint32_t aB = sb + (uint32_t)(wm * 64) * 80u;
        const uint32_t bB = sb + 20480u + (uint32_t)(wn * 64) * 80u;
#pragma unroll
        for (int ks = 0; ks < 2; ks++) {
            uint32_t ah[4][4], al[4][4];
#pragma unroll
            for (int mf = 0; mf < 4; mf++) {
                uint32_t ad = aB + (uint32_t)(mf * 16 + (lane & 15)) * 80u
                                 + (uint32_t)(ks * 2 + (lane >> 4)) * 16u;
                LDSM4(ah[mf], ad);
                LDSM4(al[mf], ad + 10240u);
            }
#pragma unroll
            for (int np = 0; np < 4; np++) {
                uint32_t bd = bB + (uint32_t)(np * 16 + ((lane >> 4) << 3) + (lane & 7)) * 80u
                                 + (uint32_t)(ks * 2 + ((lane >> 3) & 1)) * 16u;
                uint32_t bh[4], bl[4];
                LDSM4(bh, bd);
                LDSM4(bl, bd + 20480u);
#pragma unroll
                for (int mf = 0; mf < 4; mf++) {
                    MMA_BF16(acc[mf][2 * np],     ah[mf], bh[0], bh[1]);
                    MMA_BF16(acc[mf][2 * np + 1], ah[mf], bh[2], bh[3]);
                    MMA_BF16(acc[mf][2 * np],     ah[mf], bl[0], bl[1]);
                    MMA_BF16(acc[mf][2 * np + 1], ah[mf], bl[2], bl[3]);
                    MMA_BF16(acc[mf][2 * np],     al[mf], bh[0], bh[1]);
                    MMA_BF16(acc[mf][2 * np + 1], al[mf], bh[2], bh[3]);
                }
            }
        }
        __syncthreads();
    }

    // epilogue
    const int gid = lane >> 2, tig = lane & 3;
    float* Cb = C + sC * b;
    const float* Rb = R ? (R + sC * b) : (const float*)0;
    const int rowbase = bm * BM + wm * 64;
    const int colbase = bn * BN + wn * 64;
#pragma unroll
    for (int mf = 0; mf < 4; mf++) {
        const int r0 = rowbase + mf * 16 + gid;
#pragma unroll
        for (int nf = 0; nf < 8; nf++) {
            const int col = colbase + nf * 8 + tig * 2;
            float2 v0 = make_float2(acc[mf][nf][0], acc[mf][nf][1]);
            float2 v1 = make_float2(acc[mf][nf][2], acc[mf][nf][3]);
            size_t o0 = (size_t)r0 * ldc + col;
            size_t o1 = (size_t)(r0 + 8) * ldc + col;
            if (Rb) {
                float2 q0 = *(const float2*)(Rb + o0);
                float2 q1 = *(const float2*)(Rb + o1);
                v0.x += q0.x; v0.y += q0.y; v1.x += q1.x; v1.y += q1.y;
            }
            *(float2*)(Cb + o0) = v0;
            *(float2*)(Cb + o1) = v1;
        }
    }
}

// ================= elementwise / transpose-split kernels ==========================
__global__ void k_wsplit(const float* __restrict__ wphi, const float* __restrict__ wtheta,
                         const float* __restrict__ wg, const float* __restrict__ wmask) {
    int idx = blockIdx.x * 256 + threadIdx.x;
    if (idx < 768 * 512) {
        int m = idx >> 9;
        float v;
        if (m < 256)      v = wtheta[idx];
        else if (m < 512) v = wphi[idx - 256 * 512];
        else              v = wg[idx - 512 * 512];
        uint32_t h = pack_bf(v, 0.f);
        g_Wp_h[idx] = __float2bfloat16(v);
        g_Wp_l[idx] = __float2bfloat16(v - bf_lo(h));
    } else {
        int i2 = idx - 768 * 512;
        if (i2 < 512 * 256) {
            float v = wmask[i2];
            uint32_t h = pack_bf(v, 0.f);
            g_Wm_h[i2] = __float2bfloat16(v);
            g_Wm_l[i2] = __float2bfloat16(v - bf_lo(h));
        }
    }
}

// x (b,512,4096) -> Xt_hi/lo [b][hw][c]
__global__ __launch_bounds__(256) void k_xt(const float* __restrict__ x) {
    __shared__ float s[64][65];
    int b = blockIdx.z, c0 = blockIdx.y * 64, hw0 = blockIdx.x * 64;
    int tid = threadIdx.x;
    const float* src = x + ((size_t)b * CH + c0) * HW + hw0;
#pragma unroll
    for (int i = 0; i < 4; i++) {
        int v = tid + i * 256;
        int row = v >> 4, q = v & 15;
        float4 d = *(const float4*)(src + (size_t)row * HW + q * 4);
        s[row][q * 4 + 0] = d.x; s[row][q * 4 + 1] = d.y;
        s[row][q * 4 + 2] = d.z; s[row][q * 4 + 3] = d.w;
    }
    __syncthreads();
    int h = tid >> 2, g = tid & 3;
    float v[16];
#pragma unroll
    for (int j = 0; j < 16; j++) v[j] = s[g * 16 + j][h];
    uint32_t hp[8], lp[8];
    split16(v, hp, lp);
    size_t ob = ((size_t)b * HW + hw0 + h) * CH + c0 + g * 16;
    *(uint4*)(g_Xt_h + ob) = *(uint4*)hp; *(uint4*)(g_Xt_h + ob + 8) = *(uint4*)(hp + 4);
    *(uint4*)(g_Xt_l + ob) = *(uint4*)lp; *(uint4*)(g_Xt_l + ob + 8) = *(uint4*)(lp + 4);
}

// tpg theta/phi rows -> Tt/Pt [b][i][k]
__global__ __launch_bounds__(256) void k_tpsplit() {
    __shared__ float s[64][65];
    int b = blockIdx.z;
    int which = blockIdx.y >> 3, k0 = (blockIdx.y & 7) * 64, i0 = blockIdx.x * 64;
    int tid = threadIdx.x;
    const float* base = g_tpg + (size_t)b * 768 * HW + (size_t)(which ? 256 : 0) * HW;
#pragma unroll
    for (int i = 0; i < 4; i++) {
        int v = tid + i * 256;
        int kk = v >> 4, q = v & 15;
        int ks = k0 + kk;
        float4 d = *(const float4*)(base + (size_t)(ks >> 1) * HW + (ks & 1) * NN + i0 + q * 4);
        s[kk][q * 4 + 0] = d.x; s[kk][q * 4 + 1] = d.y;
        s[kk][q * 4 + 2] = d.z; s[kk][q * 4 + 3] = d.w;
    }
    __syncthreads();
    int h = tid >> 2, g = tid & 3;
    float v[16];
#pragma unroll
    for (int j = 0; j < 16; j++) v[j] = s[g * 16 + j][h];
    uint32_t hp[8], lp[8];
    split16(v, hp, lp);
    size_t ob = ((size_t)b * NN + i0 + h) * CH + k0 + g * 16;
    __nv_bfloat16* oh = which ? g_Pt_h : g_Tt_h;
    __nv_bfloat16* ol = which ? g_Pt_l : g_Tt_l;
    *(uint4*)(oh + ob) = *(uint4*)hp; *(uint4*)(oh + ob + 8) = *(uint4*)(hp + 4);
    *(uint4*)(ol + ob) = *(uint4*)lp; *(uint4*)(ol + ob + 8) = *(uint4*)(lp + 4);
}

// tpg g rows -> Gv_hi/lo [b][c][j]
__global__ void k_gsplit() {
    size_t f = ((size_t)blockIdx.x * 256 + threadIdx.x) * 4;
    int b = (int)(f >> 20);
    size_t rem = f & 1048575;
    const float* src = g_tpg + (size_t)b * 768 * HW + (size_t)512 * HW + rem;
    float4 d = *(const float4*)src;
    uint32_t h01 = pack_bf(d.x, d.y), h23 = pack_bf(d.z, d.w);
    uint32_t l01 = pack_bf(d.x - bf_lo(h01), d.y - bf_hi(h01));
    uint32_t l23 = pack_bf(d.z - bf_lo(h23), d.w - bf_hi(h23));
    *(uint2*)(g_Gv_h + f) = make_uint2(h01, h23);
    *(uint2*)(g_Gv_l + f) = make_uint2(l01, l23);
}

// segmented column softmax stats (softmax over rows i, per column j)
__global__ void k_stats_part() {
    int b = blockIdx.z, seg = blockIdx.y;
    int j = blockIdx.x * 256 + threadIdx.x;
    const float* p = g_attn + (size_t)b * NN * NN + (size_t)(seg * 256) * NN + j;
    float m = -INFINITY, s = 0.f;
    for (int i = 0; i < 256; i++) {
        float v = p[(size_t)i * NN];
        float nm = fmaxf(m, v);
        s = s * __expf(m - nm) + __expf(v - nm);
        m = nm;
    }
    g_pm[(seg * BB + b) * NN + j] = m;
    g_ps[(seg * BB + b) * NN + j] = s;
}
__global__ void k_stats_comb() {
    int b = blockIdx.y;
    int j = blockIdx.x * 256 + threadIdx.x;
    float M = -INFINITY;
#pragma unroll
    for (int s = 0; s < 8; s++) M = fmaxf(M, g_pm[(s * BB + b) * NN + j]);
    float S = 0.f;
#pragma unroll
    for (int s = 0; s < 8; s++)
        S += g_ps[(s * BB + b) * NN + j] * __expf(g_pm[(s * BB + b) * NN + j] - M);
    g_m[b * NN + j] = M;
    g_rinv[b * NN + j] = 1.f / S;
}

// P = softmax(attn) split to bf16 hi/lo
__global__ void k_psplit() {
    size_t f = ((size_t)blockIdx.x * 256 + threadIdx.x) * 4;
    int b = (int)(f >> 22);
    int j = (int)(f & 2047);
    float4 a = *(const float4*)(g_attn + f);
    float4 mv = *(const float4*)(g_m + b * NN + j);
    float4 rv = *(const float4*)(g_rinv + b * NN + j);
    float e0 = __expf(a.x - mv.x) * rv.x;
    float e1 = __expf(a.y - mv.y) * rv.y;
    float e2 = __expf(a.z - mv.z) * rv.z;
    float e3 = __expf(a.w - mv.w) * rv.w;
    uint32_t h01 = pack_bf(e0, e1), h23 = pack_bf(e2, e3);
    uint32_t l01 = pack_bf(e0 - bf_lo(h01), e1 - bf_hi(h01));
    uint32_t l23 = pack_bf(e2 - bf_lo(h23), e3 - bf_hi(h23));
    *(uint2*)(g_P_h + f) = make_uint2(h01, h23);
    *(uint2*)(g_P_l + f) = make_uint2(l01, l23);
}

// y [b][c][i] -> Yt_hi/lo [b][hw][c2]
__global__ __launch_bounds__(256) void k_ysplit() {
    __shared__ float s[64][65];
    int b = blockIdx.z, c20 = blockIdx.y * 64, hw0 = blockIdx.x * 64;
    int half = (hw0 >= 2048) ? 1 : 0, i0 = hw0 & 2047;
    int tid = threadIdx.x;
    const float* base = g_y + (size_t)b * CH * NN;
#pragma unroll
    for (int i = 0; i < 4; i++) {
        int v = tid + i * 256;
        int cc = v >> 4, q = v & 15;
        float4 d = *(const float4*)(base + (size_t)(2 * (c20 + cc) + half) * NN + i0 + q * 4);
        s[cc][q * 4 + 0] = d.x; s[cc][q * 4 + 1] = d.y;
        s[cc][q * 4 + 2] = d.z; s[cc][q * 4 + 3] = d.w;
    }
    __syncthreads();
    int h = tid >> 2, g = tid & 3;
    float v[16];
#pragma unroll
    for (int j = 0; j < 16; j++) v[j] = s[g * 16 + j][h];
    uint32_t hp[8], lp[8];
    split16(v, hp, lp);
    size_t ob = ((size_t)b * HW + hw0 + h) * 256 + c20 + g * 16;
    *(uint4*)(g_Yt_h + ob) = *(uint4*)hp; *(uint4*)(g_Yt_h + ob + 8) = *(uint4*)(hp + 4);
    *(uint4*)(g_Yt_l + ob) = *(uint4*)lp; *(uint4*)(g_Yt_l + ob + 8) = *(uint4*)(lp + 4);
}

// ================= launch =========================================================
extern "C" void kernel_launch(void* const* d_in, const int* in_sizes, int n_in,
                              void* d_out, int out_size) {
    const float* x      = (const float*)d_in[0];
    const float* wphi   = (const float*)d_in[1];
    const float* wtheta = (const float*)d_in[2];
    const float* wg     = (const float*)d_in[3];
    const float* wmask  = (const float*)d_in[4];
    float* out = (float*)d_out;

    cudaFuncSetAttribute(gemm_bf16x3, cudaFuncAttributeMaxDynamicSharedMemorySize, GEMM_SMEM);

    __nv_bfloat16 *Wp_h, *Wp_l, *Wm_h, *Wm_l, *Xt_h, *Xt_l, *Tt_h, *Tt_l, *Pt_h, *Pt_l;
    __nv_bfloat16 *Gv_h, *Gv_l, *P_h, *P_l, *Yt_h, *Yt_l;
    float *tpg, *attn, *y;
    cudaGetSymbolAddress((void**)&Wp_h, g_Wp_h); cudaGetSymbolAddress((void**)&Wp_l, g_Wp_l);
    cudaGetSymbolAddress((void**)&Wm_h, g_Wm_h); cudaGetSymbolAddress((void**)&Wm_l, g_Wm_l);
    cudaGetSymbolAddress((void**)&Xt_h, g_Xt_h); cudaGetSymbolAddress((void**)&Xt_l, g_Xt_l);
    cudaGetSymbolAddress((void**)&Tt_h, g_Tt_h); cudaGetSymbolAddress((void**)&Tt_l, g_Tt_l);
    cudaGetSymbolAddress((void**)&Pt_h, g_Pt_h); cudaGetSymbolAddress((void**)&Pt_l, g_Pt_l);
    cudaGetSymbolAddress((void**)&Gv_h, g_Gv_h); cudaGetSymbolAddress((void**)&Gv_l, g_Gv_l);
    cudaGetSymbolAddress((void**)&P_h, g_P_h);   cudaGetSymbolAddress((void**)&P_l, g_P_l);
    cudaGetSymbolAddress((void**)&Yt_h, g_Yt_h); cudaGetSymbolAddress((void**)&Yt_l, g_Yt_l);
    cudaGetSymbolAddress((void**)&tpg, g_tpg);
    cudaGetSymbolAddress((void**)&attn, g_attn);
    cudaGetSymbolAddress((void**)&y, g_y);

    // 1. weight splits + x transpose-split
    k_wsplit<<<2048, 256>>>(wphi, wtheta, wg, wmask);
    k_xt<<<dim3(64, 8, BB), 256>>>(x);
    // 2. conv GEMM: tpg[b](768x4096) = Wp(768x512) @ Xt[b]^T
    gemm_bf16x3<<<dim3(16, 6, BB), 256, GEMM_SMEM>>>(
        Wp_h, Wp_l, Xt_h, Xt_l, tpg, nullptr, 512, 4096, 0, (size_t)HW * CH, (size_t)768 * HW);
    // 3. view-transpose splits of theta/phi and g
    k_tpsplit<<<dim3(32, 16, BB), 256>>>();
    k_gsplit<<<8192, 256>>>();
    // 4. attn GEMM: attn[b](2048x2048) = Tt @ Pt^T (K=512)
    gemm_bf16x3<<<dim3(8, 16, BB), 256, GEMM_SMEM>>>(
        Tt_h, Tt_l, Pt_h, Pt_l, attn, nullptr, 512, 2048,
        (size_t)NN * CH, (size_t)NN * CH, (size_t)NN * NN);
    // 5. column softmax stats + P split
    k_stats_part<<<dim3(8, 8, BB), 256>>>();
    k_stats_comb<<<dim3(8, BB), 256>>>();
    k_psplit<<<32768, 256>>>();
    // 6. av GEMM: y[b](512x2048) = Gv @ P^T (K=2048)
    gemm_bf16x3<<<dim3(8, 4, BB), 256, GEMM_SMEM>>>(
        Gv_h, Gv_l, P_h, P_l, y, nullptr, 2048, 2048,
        (size_t)CH * NN, (size_t)NN * NN, (size_t)CH * NN);
    // 7. y view-transpose split
    k_ysplit<<<dim3(64, 4, BB), 256>>>();
    // 8. mask GEMM + residual: out[b](512x4096) = Wm(512x256) @ Yt^T + x
    gemm_bf16x3<<<dim3(16, 4, BB), 256, GEMM_SMEM>>>(
        Wm_h, Wm_l, Yt_h, Yt_l, out, x, 256, 4096, 0, (size_t)HW * 256, (size_t)CH * HW);
}